// round 3
// baseline (speedup 1.0000x reference)
#include <cuda_runtime.h>
#include <cuda_bf16.h>
#include <math.h>

// Problem dims
#define TT   128
#define BB   256
#define NN   (TT*BB)        // 32768
#define HID  128
#define G4   512            // 4*HID
#define NFLAT 1024
#define NA   7

// ---------------- scratch (device globals, no allocation) ----------------
// __align__(16): these are accessed through float4* — element-type alignment
// (4B) is NOT sufficient and caused the R1 misaligned-address fault.
__device__ __align__(16) float g_feat[NN * NFLAT];   // 134 MB
__device__ __align__(16) float g_pre [NN * G4];      // 67 MB
__device__ __align__(16) float g_hid [NN * HID];     // 16.8 MB

// ---------------- Kernel 1: fused conv stack -> feat ----------------
// block = one sample, 128 threads
__global__ __launch_bounds__(128) void conv_feat_kernel(
    const float* __restrict__ obs,
    const float* __restrict__ w1, const float* __restrict__ b1,
    const float* __restrict__ w2, const float* __restrict__ b2,
    const float* __restrict__ w3, const float* __restrict__ b3)
{
    __shared__ float xs[3][7][7];                     // scalar access only
    __shared__ float c1[16][6][6];
    __shared__ float c2[32][5][5];
    __shared__ __align__(16) float w2s[32*16*4];      // float4 access
    __shared__ __align__(16) float w3s[64*32*4];      // float4 access

    const int n = blockIdx.x;
    const int tid = threadIdx.x;

    // stage conv2/conv3 weights (L2-hot, coalesced float4)
    {
        const float4* s2 = (const float4*)w2;
        float4* d2 = (float4*)w2s;
        for (int i = tid; i < 32*16; i += 128) d2[i] = s2[i];
        const float4* s3 = (const float4*)w3;
        float4* d3 = (float4*)w3s;
        for (int i = tid; i < 64*32; i += 128) d3[i] = s3[i];
    }
    // load obs NHWC -> CHW
    const float* ob = obs + n * 147;
    for (int i = tid; i < 147; i += 128) {
        int h = i / 21, r = i % 21, w = r / 3, c = r % 3;
        xs[c][h][w] = ob[i];
    }
    __syncthreads();

    // conv1: 16x6x6, 3ch 2x2 (w1 reads are 16B-offset from input base)
    for (int i = tid; i < 576; i += 128) {
        int o = i / 36, r = i % 36, y = r / 6, x = r % 6;
        float s = __ldg(&b1[o]);
        #pragma unroll
        for (int c = 0; c < 3; c++) {
            const float* wp = &w1[((o*3 + c) * 2) * 2];
            float4 wv = *(const float4*)wp;
            s += xs[c][y  ][x] * wv.x + xs[c][y  ][x+1] * wv.y
               + xs[c][y+1][x] * wv.z + xs[c][y+1][x+1] * wv.w;
        }
        c1[o][y][x] = fmaxf(s, 0.f);
    }
    __syncthreads();

    // conv2: 32x5x5, 16ch 2x2
    for (int i = tid; i < 800; i += 128) {
        int o = i / 25, r = i % 25, y = r / 5, x = r % 5;
        float s = __ldg(&b2[o]);
        #pragma unroll
        for (int c = 0; c < 16; c++) {
            float4 wv = *(const float4*)&w2s[(o*16 + c) * 4];
            s += c1[c][y  ][x] * wv.x + c1[c][y  ][x+1] * wv.y
               + c1[c][y+1][x] * wv.z + c1[c][y+1][x+1] * wv.w;
        }
        c2[o][y][x] = fmaxf(s, 0.f);
    }
    __syncthreads();

    // conv3: 64x4x4, 32ch 2x2 -> feat
    float* fo = g_feat + (size_t)n * NFLAT;
    for (int i = tid; i < 1024; i += 128) {
        int o = i / 16, r = i % 16, y = r / 4, x = r % 4;
        float s = __ldg(&b3[o]);
        #pragma unroll
        for (int c = 0; c < 32; c++) {
            float4 wv = *(const float4*)&w3s[(o*32 + c) * 4];
            s += c2[c][y  ][x] * wv.x + c2[c][y  ][x+1] * wv.y
               + c2[c][y+1][x] * wv.z + c2[c][y+1][x+1] * wv.w;
        }
        fo[i] = fmaxf(s, 0.f);
    }
}

// ---------------- Kernel 2: pre = feat @ w_ih^T + (b_ih+b_hh) ----------------
// C[N=32768][J=512], K=1024. BM=128 BN=64 BK=16, 256 threads, 8x4 micro-tile.
__global__ __launch_bounds__(256) void gemm_pre_kernel(
    const float* __restrict__ w_ih,
    const float* __restrict__ b_ih, const float* __restrict__ b_hh)
{
    __shared__ __align__(16) float As[16][132];   // 528B row stride (÷16)
    __shared__ __align__(16) float Bs[16][68];    // 272B row stride (÷16)

    const int tid  = threadIdx.x;
    const int row0 = blockIdx.y * 128;
    const int col0 = blockIdx.x * 64;
    const int tm = (tid / 16) * 8;
    const int tn = (tid % 16) * 4;

    float acc[8][4];
    #pragma unroll
    for (int i = 0; i < 8; i++)
        #pragma unroll
        for (int j = 0; j < 4; j++) acc[i][j] = 0.f;

    const float* A = g_feat;
    for (int kt = 0; kt < NFLAT; kt += 16) {
        #pragma unroll
        for (int l = 0; l < 2; l++) {
            int pos = tid + l * 256;
            int m = pos >> 2, kq = (pos & 3) * 4;
            float4 v = *(const float4*)(A + (size_t)(row0 + m) * NFLAT + kt + kq);
            As[kq + 0][m] = v.x; As[kq + 1][m] = v.y;
            As[kq + 2][m] = v.z; As[kq + 3][m] = v.w;
        }
        {
            int j = tid >> 2, kq = (tid & 3) * 4;
            float4 v = *(const float4*)(w_ih + (size_t)(col0 + j) * NFLAT + kt + kq);
            Bs[kq + 0][j] = v.x; Bs[kq + 1][j] = v.y;
            Bs[kq + 2][j] = v.z; Bs[kq + 3][j] = v.w;
        }
        __syncthreads();
        #pragma unroll
        for (int kk = 0; kk < 16; kk++) {
            float4 a0 = *(const float4*)&As[kk][tm];
            float4 a1 = *(const float4*)&As[kk][tm + 4];
            float4 bv = *(const float4*)&Bs[kk][tn];
            float a[8] = {a0.x, a0.y, a0.z, a0.w, a1.x, a1.y, a1.z, a1.w};
            float b[4] = {bv.x, bv.y, bv.z, bv.w};
            #pragma unroll
            for (int i = 0; i < 8; i++)
                #pragma unroll
                for (int j = 0; j < 4; j++)
                    acc[i][j] = fmaf(a[i], b[j], acc[i][j]);
        }
        __syncthreads();
    }

    #pragma unroll
    for (int i = 0; i < 8; i++) {
        int nrow = row0 + tm + i;
        #pragma unroll
        for (int j = 0; j < 4; j++) {
            int jj = col0 + tn + j;
            g_pre[(size_t)nrow * G4 + jj] = acc[i][j] + __ldg(&b_ih[jj]) + __ldg(&b_hh[jj]);
        }
    }
}

// ---------------- Kernel 3: persistent LSTM, 2 batch rows / block ----------------
#define RC 64   // weights cached in registers per thread
__global__ __launch_bounds__(512, 1) void lstm_kernel(
    const float* __restrict__ done,
    const float* __restrict__ h0, const float* __restrict__ c0,
    const float* __restrict__ w_hh,
    float* __restrict__ hT, float* __restrict__ cT)
{
    __shared__ float hs[2][128];
    __shared__ float cs[2][128];
    __shared__ float gs[2][512];

    const int tid = threadIdx.x;          // 512: one gate row each
    const int b0  = blockIdx.x * 2;

    if (tid < 256) {
        int r = tid >> 7, u = tid & 127;
        hs[r][u] = h0[(b0 + r) * HID + u];
        cs[r][u] = c0[(b0 + r) * HID + u];
    }

    const float* wrow = w_hh + (size_t)tid * HID;   // input base: aligned
    float wc[RC];
    #pragma unroll
    for (int k = 0; k < RC; k++) wc[k] = wrow[k];
    __syncthreads();

    for (int t = 0; t < TT; t++) {
        if (tid < 256) {
            int r = tid >> 7, u = tid & 127;
            float m = 1.f - done[t * BB + b0 + r];
            hs[r][u] *= m;
            cs[r][u] *= m;
        }
        __syncthreads();

        float a0 = g_pre[((size_t)(t * BB + b0    )) * G4 + tid];
        float a1 = g_pre[((size_t)(t * BB + b0 + 1)) * G4 + tid];
        #pragma unroll
        for (int k = 0; k < RC; k++) {
            float w = wc[k];
            a0 = fmaf(w, hs[0][k], a0);
            a1 = fmaf(w, hs[1][k], a1);
        }
        #pragma unroll
        for (int k = RC; k < HID; k += 4) {
            float4 wv = *(const float4*)(wrow + k);
            a0 = fmaf(wv.x, hs[0][k], a0);   a0 = fmaf(wv.y, hs[0][k+1], a0);
            a0 = fmaf(wv.z, hs[0][k+2], a0); a0 = fmaf(wv.w, hs[0][k+3], a0);
            a1 = fmaf(wv.x, hs[1][k], a1);   a1 = fmaf(wv.y, hs[1][k+1], a1);
            a1 = fmaf(wv.z, hs[1][k+2], a1); a1 = fmaf(wv.w, hs[1][k+3], a1);
        }
        gs[0][tid] = a0;
        gs[1][tid] = a1;
        __syncthreads();

        if (tid < 256) {
            int r = tid >> 7, u = tid & 127;
            float ig = 1.f / (1.f + __expf(-gs[r][u]));
            float fg = 1.f / (1.f + __expf(-gs[r][128 + u]));
            float gg = tanhf(gs[r][256 + u]);
            float og = 1.f / (1.f + __expf(-gs[r][384 + u]));
            float c = fg * cs[r][u] + ig * gg;
            float h = og * tanhf(c);
            cs[r][u] = c;
            hs[r][u] = h;
            g_hid[((size_t)(t * BB + b0 + r)) * HID + u] = h;
        }
        __syncthreads();
    }

    if (tid < 256) {
        int r = tid >> 7, u = tid & 127;
        hT[(b0 + r) * HID + u] = hs[r][u];
        cT[(b0 + r) * HID + u] = cs[r][u];
    }
}

// ---------------- Kernel 4: heads -> out[N,8] ----------------
// block = 16 samples, 128 threads
__global__ __launch_bounds__(128) void heads_kernel(
    const float* __restrict__ aw, const float* __restrict__ ab,
    const float* __restrict__ cw, const float* __restrict__ cb,
    float* __restrict__ out)
{
    __shared__ __align__(16) float ws [8][132];
    __shared__ __align__(16) float hsm[16][132];
    __shared__ float bs[8];

    const int tid = threadIdx.x;
    const int n0 = blockIdx.x * 16;

    for (int i = tid; i < NA * HID; i += 128) ws[i >> 7][i & 127] = aw[i];
    ws[7][tid] = cw[tid];
    if (tid < NA) bs[tid] = ab[tid];
    if (tid == NA) bs[7] = cb[0];

    for (int i = tid; i < 16 * HID; i += 128)
        hsm[i >> 7][i & 127] = g_hid[(size_t)n0 * HID + i];
    __syncthreads();

    const int s = tid >> 3, col = tid & 7;
    float acc = bs[col];
    const float4* hp = (const float4*)&hsm[s][0];
    const float4* wp = (const float4*)&ws[col][0];
    #pragma unroll
    for (int k = 0; k < 32; k++) {
        float4 h4 = hp[k], w4 = wp[k];
        acc += h4.x * w4.x + h4.y * w4.y + h4.z * w4.z + h4.w * w4.w;
    }
    out[(size_t)(n0 + s) * 8 + col] = acc;
}

// ---------------- launch ----------------
extern "C" void kernel_launch(void* const* d_in, const int* in_sizes, int n_in,
                              void* d_out, int out_size)
{
    const float* obs   = (const float*)d_in[0];
    const float* done  = (const float*)d_in[1];
    const float* h0    = (const float*)d_in[2];
    const float* c0    = (const float*)d_in[3];
    const float* w1    = (const float*)d_in[4];
    const float* b1    = (const float*)d_in[5];
    const float* w2    = (const float*)d_in[6];
    const float* b2    = (const float*)d_in[7];
    const float* w3    = (const float*)d_in[8];
    const float* b3    = (const float*)d_in[9];
    const float* w_ih  = (const float*)d_in[10];
    const float* w_hh  = (const float*)d_in[11];
    const float* b_ih  = (const float*)d_in[12];
    const float* b_hh  = (const float*)d_in[13];
    const float* aw    = (const float*)d_in[14];
    const float* ab    = (const float*)d_in[15];
    const float* cw    = (const float*)d_in[16];
    const float* cb    = (const float*)d_in[17];

    float* out = (float*)d_out;                    // [N, 8]
    float* hT  = out + (size_t)NN * 8;             // [B, HID]
    float* cT  = hT + (size_t)BB * HID;            // [B, HID]

    conv_feat_kernel<<<NN, 128>>>(obs, w1, b1, w2, b2, w3, b3);

    dim3 ggrid(G4 / 64, NN / 128);
    gemm_pre_kernel<<<ggrid, 256>>>(w_ih, b_ih, b_hh);

    lstm_kernel<<<BB / 2, 512>>>(done, h0, c0, w_hh, hT, cT);

    heads_kernel<<<NN / 16, 128>>>(aw, ab, cw, cb, out);
}

// round 4
// speedup vs baseline: 1.5831x; 1.5831x over previous
#include <cuda_runtime.h>
#include <cuda_bf16.h>
#include <math.h>

// Problem dims
#define TT   128
#define BB   256
#define NN   (TT*BB)        // 32768
#define HID  128
#define G4   512            // 4*HID
#define NFLAT 1024
#define NA   7

// ---------------- scratch (device globals, no allocation) ----------------
__device__ __align__(16) float g_feat[NN * NFLAT];   // 134 MB
__device__ __align__(16) float g_pre [NN * G4];      // 67 MB
__device__ __align__(16) float g_hid [NN * HID];     // 16.8 MB

// ---------------- Kernel 1: fused conv stack, 4 samples/block ----------------
// 128 threads. Dynamic smem layout (floats):
//   XS  = 0      : 4 * 147            (obs, CHW per sample)
//   C1  = 588    : 4 * 577            (16x6x6 padded stride 577 vs bank collapse)
//   C2  = 2896   : 4 * 801            (32x5x5 padded stride 801)
//   W2  = 6100   : 2048               (float4-aligned: 6100*4 % 16 == 0)
//   W3  = 8148   : 8192               (float4-aligned)
#define CV_XS 0
#define CV_C1 588
#define CV_S1 577
#define CV_C2 2896
#define CV_S2 801
#define CV_W2 6100
#define CV_W3 8148
#define CV_SMEM_FLOATS (CV_W3 + 8192)
#define CV_SMEM_BYTES  (CV_SMEM_FLOATS * 4)

__global__ __launch_bounds__(128) void conv_feat_kernel(
    const float* __restrict__ obs,
    const float* __restrict__ w1, const float* __restrict__ b1,
    const float* __restrict__ w2, const float* __restrict__ b2,
    const float* __restrict__ w3, const float* __restrict__ b3)
{
    extern __shared__ __align__(16) float sm[];
    const int tid = threadIdx.x;
    const int n0 = blockIdx.x * 4;

    // stage conv2/conv3 weights (coalesced float4)
    {
        const float4* s2 = (const float4*)w2;
        float4* d2 = (float4*)(sm + CV_W2);
        for (int i = tid; i < 32*16; i += 128) d2[i] = s2[i];
        const float4* s3 = (const float4*)w3;
        float4* d3 = (float4*)(sm + CV_W3);
        for (int i = tid; i < 64*32; i += 128) d3[i] = s3[i];
    }
    // load obs for 4 samples, NHWC -> CHW
    for (int i = tid; i < 4*147; i += 128) {
        int s = i / 147, r = i % 147;
        int h = r / 21, q = r % 21, w = q / 3, c = q % 3;
        sm[CV_XS + s*147 + c*49 + h*7 + w] = obs[(size_t)n0 * 147 + i];
    }
    __syncthreads();

    // conv1: 16 x 6x6, 3ch 2x2   (4*576 = 2304 outputs = 18 per thread)
    for (int i = tid; i < 4*576; i += 128) {
        int s = i / 576, r = i % 576;
        int o = r / 36, q = r % 36, y = q / 6, x = q % 6;
        float acc = __ldg(&b1[o]);
        #pragma unroll
        for (int c = 0; c < 3; c++) {
            float4 wv = *(const float4*)&w1[(o*3 + c) * 4];
            const float* xb = sm + CV_XS + s*147 + c*49 + y*7 + x;
            acc += xb[0] * wv.x + xb[1] * wv.y + xb[7] * wv.z + xb[8] * wv.w;
        }
        sm[CV_C1 + s*CV_S1 + o*36 + y*6 + x] = fmaxf(acc, 0.f);
    }
    __syncthreads();

    // conv2: 32 x 5x5, 16ch 2x2. thread = (pos, sample), all 32 o's in regs.
    if (tid < 100) {
        int pos = tid >> 2, s = tid & 3;
        int y = pos / 5, x = pos % 5;
        float acc[32];
        #pragma unroll
        for (int o = 0; o < 32; o++) acc[o] = __ldg(&b2[o]);
        const float4* w2v = (const float4*)(sm + CV_W2);
        #pragma unroll 4
        for (int c = 0; c < 16; c++) {
            const float* xb = sm + CV_C1 + s*CV_S1 + c*36 + y*6 + x;
            float aa = xb[0], ab = xb[1], ac = xb[6], ad = xb[7];
            #pragma unroll
            for (int o = 0; o < 32; o++) {
                float4 wv = w2v[o*16 + c];           // warp-broadcast
                acc[o] += aa*wv.x + ab*wv.y + ac*wv.z + ad*wv.w;
            }
        }
        #pragma unroll
        for (int o = 0; o < 32; o++)
            sm[CV_C2 + s*CV_S2 + o*25 + pos] = fmaxf(acc[o], 0.f);
    }
    __syncthreads();

    // conv3: 64 x 4x4, 32ch 2x2. thread = (half, sample, pos), 32 o's in regs.
    {
        int half = tid >> 6, rem = tid & 63;
        int s = rem >> 4, pos = rem & 15;
        int y = pos >> 2, x = pos & 3;
        int o0 = half * 32;
        float acc[32];
        #pragma unroll
        for (int o = 0; o < 32; o++) acc[o] = __ldg(&b3[o0 + o]);
        const float4* w3v = (const float4*)(sm + CV_W3);
        #pragma unroll 4
        for (int c = 0; c < 32; c++) {
            const float* xb = sm + CV_C2 + s*CV_S2 + c*25 + y*5 + x;
            float aa = xb[0], ab = xb[1], ac = xb[5], ad = xb[6];
            #pragma unroll
            for (int o = 0; o < 32; o++) {
                float4 wv = w3v[(o0 + o)*32 + c];    // warp-broadcast
                acc[o] += aa*wv.x + ab*wv.y + ac*wv.z + ad*wv.w;
            }
        }
        float* fo = g_feat + (size_t)(n0 + s) * NFLAT;
        #pragma unroll
        for (int o = 0; o < 32; o++)
            fo[(o0 + o)*16 + pos] = fmaxf(acc[o], 0.f);
    }
}

// ---------------- Kernel 2: tf32 tensor-core GEMM ----------------
// pre[N=32768, 512] = feat[N,1024] @ w_ih^T[1024,512] + bias
// BM=128 BN=128 BK=16, 256 thr (8 warps: 2 in M x 4 in N), warp tile 64x32.
// mma.sync.aligned.m16n8k8 tf32. smem [row][20] (16+4 pad): conflict-free
// fragment LDS (lr*20+lc is a permutation mod 32) and direct STS.128 staging.

__device__ __forceinline__ unsigned f2tf(float f) {
    unsigned u;
    asm("cvt.rna.tf32.f32 %0, %1;" : "=r"(u) : "f"(f));
    return u;
}

__global__ __launch_bounds__(256) void gemm_pre_kernel(
    const float* __restrict__ w_ih,
    const float* __restrict__ b_ih, const float* __restrict__ b_hh)
{
    __shared__ __align__(16) unsigned sA[128 * 20];
    __shared__ __align__(16) unsigned sB[128 * 20];

    const int tid  = threadIdx.x;
    const int lane = tid & 31;
    const int wid  = tid >> 5;
    const int lr = lane >> 2, lc = lane & 3;
    const int wm = wid & 1;          // 2 warps in M
    const int wn = wid >> 1;         // 4 warps in N
    const int row0 = blockIdx.y * 128;
    const int col0 = blockIdx.x * 128;

    float acc[4][4][4];
    #pragma unroll
    for (int mt = 0; mt < 4; mt++)
        #pragma unroll
        for (int nt = 0; nt < 4; nt++)
            #pragma unroll
            for (int r = 0; r < 4; r++) acc[mt][nt][r] = 0.f;

    for (int kt = 0; kt < NFLAT; kt += 16) {
        // stage A: 128 rows x 16 k  (512 float4, 2 per thread)
        #pragma unroll
        for (int l = 0; l < 2; l++) {
            int idx = tid + l * 256;
            int m = idx >> 2, kq = (idx & 3) * 4;
            float4 v = *(const float4*)(g_feat + (size_t)(row0 + m) * NFLAT + kt + kq);
            uint4 t = make_uint4(f2tf(v.x), f2tf(v.y), f2tf(v.z), f2tf(v.w));
            *(uint4*)&sA[m * 20 + kq] = t;
        }
        // stage B: 128 n-rows x 16 k
        #pragma unroll
        for (int l = 0; l < 2; l++) {
            int idx = tid + l * 256;
            int n = idx >> 2, kq = (idx & 3) * 4;
            float4 v = *(const float4*)(w_ih + (size_t)(col0 + n) * NFLAT + kt + kq);
            uint4 t = make_uint4(f2tf(v.x), f2tf(v.y), f2tf(v.z), f2tf(v.w));
            *(uint4*)&sB[n * 20 + kq] = t;
        }
        __syncthreads();

        #pragma unroll
        for (int ks = 0; ks < 2; ks++) {
            const int k0 = ks * 8;
            unsigned a[4][4], b[4][2];
            #pragma unroll
            for (int mt = 0; mt < 4; mt++) {
                int m0 = wm * 64 + mt * 16;
                a[mt][0] = sA[(m0 + lr    ) * 20 + k0 + lc    ];
                a[mt][1] = sA[(m0 + lr + 8) * 20 + k0 + lc    ];
                a[mt][2] = sA[(m0 + lr    ) * 20 + k0 + lc + 4];
                a[mt][3] = sA[(m0 + lr + 8) * 20 + k0 + lc + 4];
            }
            #pragma unroll
            for (int nt = 0; nt < 4; nt++) {
                int n0 = wn * 32 + nt * 8;
                b[nt][0] = sB[(n0 + lr) * 20 + k0 + lc    ];
                b[nt][1] = sB[(n0 + lr) * 20 + k0 + lc + 4];
            }
            #pragma unroll
            for (int mt = 0; mt < 4; mt++)
                #pragma unroll
                for (int nt = 0; nt < 4; nt++) {
                    asm volatile(
                        "mma.sync.aligned.m16n8k8.row.col.f32.tf32.tf32.f32 "
                        "{%0,%1,%2,%3}, {%4,%5,%6,%7}, {%8,%9}, {%0,%1,%2,%3};\n"
                        : "+f"(acc[mt][nt][0]), "+f"(acc[mt][nt][1]),
                          "+f"(acc[mt][nt][2]), "+f"(acc[mt][nt][3])
                        : "r"(a[mt][0]), "r"(a[mt][1]), "r"(a[mt][2]), "r"(a[mt][3]),
                          "r"(b[nt][0]), "r"(b[nt][1]));
                }
        }
        __syncthreads();
    }

    // epilogue: bias + store (float2, cols even)
    float bb0[4], bb1[4];
    #pragma unroll
    for (int nt = 0; nt < 4; nt++) {
        int col = col0 + wn * 32 + nt * 8 + 2 * lc;
        bb0[nt] = __ldg(&b_ih[col])     + __ldg(&b_hh[col]);
        bb1[nt] = __ldg(&b_ih[col + 1]) + __ldg(&b_hh[col + 1]);
    }
    #pragma unroll
    for (int mt = 0; mt < 4; mt++) {
        int r0 = row0 + wm * 64 + mt * 16 + lr;
        #pragma unroll
        for (int nt = 0; nt < 4; nt++) {
            int col = col0 + wn * 32 + nt * 8 + 2 * lc;
            *(float2*)&g_pre[(size_t)r0 * G4 + col] =
                make_float2(acc[mt][nt][0] + bb0[nt], acc[mt][nt][1] + bb1[nt]);
            *(float2*)&g_pre[(size_t)(r0 + 8) * G4 + col] =
                make_float2(acc[mt][nt][2] + bb0[nt], acc[mt][nt][3] + bb1[nt]);
        }
    }
}

// ---------------- Kernel 3: persistent LSTM, 2 batch rows / block ----------------
#define RC 64   // weights cached in registers per thread
__global__ __launch_bounds__(512, 1) void lstm_kernel(
    const float* __restrict__ done,
    const float* __restrict__ h0, const float* __restrict__ c0,
    const float* __restrict__ w_hh,
    float* __restrict__ hT, float* __restrict__ cT)
{
    __shared__ float hs[2][128];
    __shared__ float cs[2][128];
    __shared__ float gs[2][512];

    const int tid = threadIdx.x;          // 512: one gate row each
    const int b0  = blockIdx.x * 2;

    if (tid < 256) {
        int r = tid >> 7, u = tid & 127;
        hs[r][u] = h0[(b0 + r) * HID + u];
        cs[r][u] = c0[(b0 + r) * HID + u];
    }

    const float* wrow = w_hh + (size_t)tid * HID;
    float wc[RC];
    #pragma unroll
    for (int k = 0; k < RC; k++) wc[k] = wrow[k];
    __syncthreads();

    for (int t = 0; t < TT; t++) {
        if (tid < 256) {
            int r = tid >> 7, u = tid & 127;
            float m = 1.f - done[t * BB + b0 + r];
            hs[r][u] *= m;
            cs[r][u] *= m;
        }
        __syncthreads();

        float a0 = g_pre[((size_t)(t * BB + b0    )) * G4 + tid];
        float a1 = g_pre[((size_t)(t * BB + b0 + 1)) * G4 + tid];
        #pragma unroll
        for (int k = 0; k < RC; k++) {
            float w = wc[k];
            a0 = fmaf(w, hs[0][k], a0);
            a1 = fmaf(w, hs[1][k], a1);
        }
        #pragma unroll
        for (int k = RC; k < HID; k += 4) {
            float4 wv = *(const float4*)(wrow + k);
            a0 = fmaf(wv.x, hs[0][k], a0);   a0 = fmaf(wv.y, hs[0][k+1], a0);
            a0 = fmaf(wv.z, hs[0][k+2], a0); a0 = fmaf(wv.w, hs[0][k+3], a0);
            a1 = fmaf(wv.x, hs[1][k], a1);   a1 = fmaf(wv.y, hs[1][k+1], a1);
            a1 = fmaf(wv.z, hs[1][k+2], a1); a1 = fmaf(wv.w, hs[1][k+3], a1);
        }
        gs[0][tid] = a0;
        gs[1][tid] = a1;
        __syncthreads();

        if (tid < 256) {
            int r = tid >> 7, u = tid & 127;
            float ig = 1.f / (1.f + __expf(-gs[r][u]));
            float fg = 1.f / (1.f + __expf(-gs[r][128 + u]));
            float gg = tanhf(gs[r][256 + u]);
            float og = 1.f / (1.f + __expf(-gs[r][384 + u]));
            float c = fg * cs[r][u] + ig * gg;
            float h = og * tanhf(c);
            cs[r][u] = c;
            hs[r][u] = h;
            g_hid[((size_t)(t * BB + b0 + r)) * HID + u] = h;
        }
        __syncthreads();
    }

    if (tid < 256) {
        int r = tid >> 7, u = tid & 127;
        hT[(b0 + r) * HID + u] = hs[r][u];
        cT[(b0 + r) * HID + u] = cs[r][u];
    }
}

// ---------------- Kernel 4: heads -> out[N,8] ----------------
__global__ __launch_bounds__(128) void heads_kernel(
    const float* __restrict__ aw, const float* __restrict__ ab,
    const float* __restrict__ cw, const float* __restrict__ cb,
    float* __restrict__ out)
{
    __shared__ __align__(16) float ws [8][132];
    __shared__ __align__(16) float hsm[16][132];
    __shared__ float bs[8];

    const int tid = threadIdx.x;
    const int n0 = blockIdx.x * 16;

    for (int i = tid; i < NA * HID; i += 128) ws[i >> 7][i & 127] = aw[i];
    ws[7][tid] = cw[tid];
    if (tid < NA) bs[tid] = ab[tid];
    if (tid == NA) bs[7] = cb[0];

    for (int i = tid; i < 16 * HID; i += 128)
        hsm[i >> 7][i & 127] = g_hid[(size_t)n0 * HID + i];
    __syncthreads();

    const int s = tid >> 3, col = tid & 7;
    float acc = bs[col];
    const float4* hp = (const float4*)&hsm[s][0];
    const float4* wp = (const float4*)&ws[col][0];
    #pragma unroll
    for (int k = 0; k < 32; k++) {
        float4 h4 = hp[k], w4 = wp[k];
        acc += h4.x * w4.x + h4.y * w4.y + h4.z * w4.z + h4.w * w4.w;
    }
    out[(size_t)(n0 + s) * 8 + col] = acc;
}

// ---------------- launch ----------------
extern "C" void kernel_launch(void* const* d_in, const int* in_sizes, int n_in,
                              void* d_out, int out_size)
{
    const float* obs   = (const float*)d_in[0];
    const float* done  = (const float*)d_in[1];
    const float* h0    = (const float*)d_in[2];
    const float* c0    = (const float*)d_in[3];
    const float* w1    = (const float*)d_in[4];
    const float* b1    = (const float*)d_in[5];
    const float* w2    = (const float*)d_in[6];
    const float* b2    = (const float*)d_in[7];
    const float* w3    = (const float*)d_in[8];
    const float* b3    = (const float*)d_in[9];
    const float* w_ih  = (const float*)d_in[10];
    const float* w_hh  = (const float*)d_in[11];
    const float* b_ih  = (const float*)d_in[12];
    const float* b_hh  = (const float*)d_in[13];
    const float* aw    = (const float*)d_in[14];
    const float* ab    = (const float*)d_in[15];
    const float* cw    = (const float*)d_in[16];
    const float* cb    = (const float*)d_in[17];

    float* out = (float*)d_out;                    // [N, 8]
    float* hT  = out + (size_t)NN * 8;             // [B, HID]
    float* cT  = hT + (size_t)BB * HID;            // [B, HID]

    static bool attr_done = false;
    if (!attr_done) {
        cudaFuncSetAttribute(conv_feat_kernel,
                             cudaFuncAttributeMaxDynamicSharedMemorySize,
                             CV_SMEM_BYTES);
        attr_done = true;
    }

    conv_feat_kernel<<<NN / 4, 128, CV_SMEM_BYTES>>>(obs, w1, b1, w2, b2, w3, b3);

    dim3 ggrid(G4 / 128, NN / 128);
    gemm_pre_kernel<<<ggrid, 256>>>(w_ih, b_ih, b_hh);

    lstm_kernel<<<BB / 2, 512>>>(done, h0, c0, w_hh, hT, cT);

    heads_kernel<<<NN / 16, 128>>>(aw, ab, cw, cb, out);
}

// round 5
// speedup vs baseline: 2.2024x; 1.3912x over previous
#include <cuda_runtime.h>
#include <cuda_bf16.h>
#include <math.h>

// Problem dims
#define TT   128
#define BB   256
#define NN   (TT*BB)        // 32768
#define HID  128
#define G4   512            // 4*HID
#define NFLAT 1024
#define NA   7

// ---------------- scratch (device globals, no allocation) ----------------
__device__ __align__(16) float g_feat[NN * NFLAT];   // 134 MB (tf32-rounded fp32)
__device__ __align__(16) float g_pre [NN * G4];      // 67 MB
__device__ __align__(16) float g_hid [NN * HID];     // 16.8 MB
__device__ __align__(16) float g_wih [G4 * NFLAT];   // 2 MB  (tf32-rounded fp32)
__device__ __align__(16) float g_bias[G4];

__device__ __forceinline__ unsigned f2tf(float f) {
    unsigned u;
    asm("cvt.rna.tf32.f32 %0, %1;" : "=r"(u) : "f"(f));
    return u;
}
__device__ __forceinline__ unsigned smem_u32(const void* p) {
    unsigned r;
    asm("{ .reg .u64 t; cvta.to.shared.u64 t, %1; cvt.u32.u64 %0, t; }" : "=r"(r) : "l"(p));
    return r;
}

// ---------------- Kernel 0: prep (tf32 weights + fused bias) ----------------
__global__ __launch_bounds__(256) void prep_kernel(
    const float* __restrict__ wih,
    const float* __restrict__ bih, const float* __restrict__ bhh)
{
    int i = blockIdx.x * 256 + threadIdx.x;
    if (i < G4 * NFLAT) g_wih[i] = __uint_as_float(f2tf(wih[i]));
    if (i < G4)         g_bias[i] = bih[i] + bhh[i];
}

// ---------------- Kernel 1: fused conv stack, 4 samples/block, 256 thr ----------------
#define CV_XS 0
#define CV_C1 588
#define CV_S1 577
#define CV_C2 2896
#define CV_S2 801
#define CV_W2 6100
#define CV_W3 8148
#define CV_SMEM_FLOATS (CV_W3 + 8192)
#define CV_SMEM_BYTES  (CV_SMEM_FLOATS * 4)

__global__ __launch_bounds__(256) void conv_feat_kernel(
    const float* __restrict__ obs,
    const float* __restrict__ w1, const float* __restrict__ b1,
    const float* __restrict__ w2, const float* __restrict__ b2,
    const float* __restrict__ w3, const float* __restrict__ b3)
{
    extern __shared__ __align__(16) float sm[];
    const int tid = threadIdx.x;
    const int n0 = blockIdx.x * 4;

    // stage conv2/conv3 weights (coalesced float4)
    {
        const float4* s2 = (const float4*)w2;
        float4* d2 = (float4*)(sm + CV_W2);
        for (int i = tid; i < 32*16; i += 256) d2[i] = s2[i];
        const float4* s3 = (const float4*)w3;
        float4* d3 = (float4*)(sm + CV_W3);
        for (int i = tid; i < 64*32; i += 256) d3[i] = s3[i];
    }
    // load obs for 4 samples, NHWC -> CHW
    for (int i = tid; i < 4*147; i += 256) {
        int s = i / 147, r = i % 147;
        int h = r / 21, q = r % 21, w = q / 3, c = q % 3;
        sm[CV_XS + s*147 + c*49 + h*7 + w] = obs[(size_t)n0 * 147 + i];
    }
    __syncthreads();

    // conv1: 16 x 6x6, 3ch 2x2
    for (int i = tid; i < 4*576; i += 256) {
        int s = i / 576, r = i % 576;
        int o = r / 36, q = r % 36, y = q / 6, x = q % 6;
        float acc = __ldg(&b1[o]);
        #pragma unroll
        for (int c = 0; c < 3; c++) {
            float4 wv = *(const float4*)&w1[(o*3 + c) * 4];
            const float* xb = sm + CV_XS + s*147 + c*49 + y*7 + x;
            acc += xb[0] * wv.x + xb[1] * wv.y + xb[7] * wv.z + xb[8] * wv.w;
        }
        sm[CV_C1 + s*CV_S1 + o*36 + y*6 + x] = fmaxf(acc, 0.f);
    }
    __syncthreads();

    // conv2: 32 x 5x5, 16ch 2x2. thread = (o_half, pos, sample), 16 o's in regs.
    if (tid < 200) {
        int oh = tid / 100, rem = tid % 100;
        int pos = rem >> 2, s = rem & 3;
        int y = pos / 5, x = pos % 5;
        int o0 = oh * 16;
        float acc[16];
        #pragma unroll
        for (int o = 0; o < 16; o++) acc[o] = __ldg(&b2[o0 + o]);
        const float4* w2v = (const float4*)(sm + CV_W2);
        #pragma unroll 4
        for (int c = 0; c < 16; c++) {
            const float* xb = sm + CV_C1 + s*CV_S1 + c*36 + y*6 + x;
            float aa = xb[0], ab = xb[1], ac = xb[6], ad = xb[7];
            #pragma unroll
            for (int o = 0; o < 16; o++) {
                float4 wv = w2v[(o0 + o)*16 + c];    // warp-broadcast
                acc[o] += aa*wv.x + ab*wv.y + ac*wv.z + ad*wv.w;
            }
        }
        #pragma unroll
        for (int o = 0; o < 16; o++)
            sm[CV_C2 + s*CV_S2 + (o0 + o)*25 + pos] = fmaxf(acc[o], 0.f);
    }
    __syncthreads();

    // conv3: 64 x 4x4, 32ch 2x2. thread = (o_quarter, sample, pos), 16 o's in regs.
    {
        int q = tid >> 6, rem = tid & 63;
        int s = rem >> 4, pos = rem & 15;
        int y = pos >> 2, x = pos & 3;
        int o0 = q * 16;
        float acc[16];
        #pragma unroll
        for (int o = 0; o < 16; o++) acc[o] = __ldg(&b3[o0 + o]);
        const float4* w3v = (const float4*)(sm + CV_W3);
        #pragma unroll 4
        for (int c = 0; c < 32; c++) {
            const float* xb = sm + CV_C2 + s*CV_S2 + c*25 + y*5 + x;
            float aa = xb[0], ab = xb[1], ac = xb[5], ad = xb[6];
            #pragma unroll
            for (int o = 0; o < 16; o++) {
                float4 wv = w3v[(o0 + o)*32 + c];    // warp-broadcast (q const/warp)
                acc[o] += aa*wv.x + ab*wv.y + ac*wv.z + ad*wv.w;
            }
        }
        float* fo = g_feat + (size_t)(n0 + s) * NFLAT;
        #pragma unroll
        for (int o = 0; o < 16; o++)
            fo[(o0 + o)*16 + pos] = __uint_as_float(f2tf(fmaxf(acc[o], 0.f)));
    }
}

// ---------------- Kernel 2: tf32 tensor-core GEMM, 3-stage cp.async ----------------
// pre[N,512] = feat[N,1024] @ g_wih^T + g_bias
// BM=128 BN=128 BK=16, 256 thr (2x4 warps), warp tile 64x32, m16n8k8 tf32.
// smem [row][20] pad: STS/cp.async 16B-aligned, fragment LDS conflict-free.
#define GSTAGE 3
#define GSTRIDE 2560                    // 128*20 unsigned per operand per stage
#define G_SMEM_BYTES (GSTAGE * 2 * GSTRIDE * 4)

__global__ __launch_bounds__(256) void gemm_pre_kernel()
{
    extern __shared__ __align__(16) unsigned smg[];
    unsigned* sA = smg;                       // [GSTAGE][2560]
    unsigned* sB = smg + GSTAGE * GSTRIDE;    // [GSTAGE][2560]

    const int tid  = threadIdx.x;
    const int lane = tid & 31;
    const int wid  = tid >> 5;
    const int lr = lane >> 2, lc = lane & 3;
    const int wm = wid & 1;
    const int wn = wid >> 1;
    const int row0 = blockIdx.y * 128;
    const int col0 = blockIdx.x * 128;

    const unsigned baseA = smem_u32(sA);
    const unsigned baseB = smem_u32(sB);

    // per-thread staging coords (2 chunks of 16B per operand per stage)
    int sm0 = (tid        ) >> 2, sk0 = ((tid      ) & 3) * 4;
    int sm1 = (tid + 256  ) >> 2, sk1 = ((tid + 256) & 3) * 4;

    float acc[4][4][4];
    #pragma unroll
    for (int mt = 0; mt < 4; mt++)
        #pragma unroll
        for (int nt = 0; nt < 4; nt++)
            #pragma unroll
            for (int r = 0; r < 4; r++) acc[mt][nt][r] = 0.f;

    #define G_ISSUE(s, kt)                                                          \
    {                                                                               \
        const float* ga0 = g_feat + (size_t)(row0 + sm0) * NFLAT + (kt) + sk0;      \
        const float* ga1 = g_feat + (size_t)(row0 + sm1) * NFLAT + (kt) + sk1;      \
        const float* gb0 = g_wih  + (size_t)(col0 + sm0) * NFLAT + (kt) + sk0;      \
        const float* gb1 = g_wih  + (size_t)(col0 + sm1) * NFLAT + (kt) + sk1;      \
        unsigned da0 = baseA + ((s)*GSTRIDE + sm0*20 + sk0) * 4;                    \
        unsigned da1 = baseA + ((s)*GSTRIDE + sm1*20 + sk1) * 4;                    \
        unsigned db0 = baseB + ((s)*GSTRIDE + sm0*20 + sk0) * 4;                    \
        unsigned db1 = baseB + ((s)*GSTRIDE + sm1*20 + sk1) * 4;                    \
        asm volatile("cp.async.cg.shared.global [%0], [%1], 16;" :: "r"(da0), "l"(ga0)); \
        asm volatile("cp.async.cg.shared.global [%0], [%1], 16;" :: "r"(da1), "l"(ga1)); \
        asm volatile("cp.async.cg.shared.global [%0], [%1], 16;" :: "r"(db0), "l"(gb0)); \
        asm volatile("cp.async.cg.shared.global [%0], [%1], 16;" :: "r"(db1), "l"(gb1)); \
    }

    G_ISSUE(0, 0);
    asm volatile("cp.async.commit_group;");
    G_ISSUE(1, 16);
    asm volatile("cp.async.commit_group;");

    const int NIT = NFLAT / 16;   // 64
    for (int it = 0; it < NIT; it++) {
        const int s = it % GSTAGE;
        asm volatile("cp.async.wait_group 1;");
        __syncthreads();
        // issue stage it+2 into slot (it+2)%3 == (it-1)%3 (read finished last iter)
        if (it + 2 < NIT) {
            G_ISSUE((it + 2) % GSTAGE, (it + 2) * 16);
        }
        asm volatile("cp.async.commit_group;");

        const unsigned* pA = sA + s * GSTRIDE;
        const unsigned* pB = sB + s * GSTRIDE;
        #pragma unroll
        for (int ks = 0; ks < 2; ks++) {
            const int k0 = ks * 8;
            unsigned a[4][4], b[4][2];
            #pragma unroll
            for (int mt = 0; mt < 4; mt++) {
                int m0 = wm * 64 + mt * 16;
                a[mt][0] = pA[(m0 + lr    ) * 20 + k0 + lc    ];
                a[mt][1] = pA[(m0 + lr + 8) * 20 + k0 + lc    ];
                a[mt][2] = pA[(m0 + lr    ) * 20 + k0 + lc + 4];
                a[mt][3] = pA[(m0 + lr + 8) * 20 + k0 + lc + 4];
            }
            #pragma unroll
            for (int nt = 0; nt < 4; nt++) {
                int n0 = wn * 32 + nt * 8;
                b[nt][0] = pB[(n0 + lr) * 20 + k0 + lc    ];
                b[nt][1] = pB[(n0 + lr) * 20 + k0 + lc + 4];
            }
            #pragma unroll
            for (int mt = 0; mt < 4; mt++)
                #pragma unroll
                for (int nt = 0; nt < 4; nt++) {
                    asm volatile(
                        "mma.sync.aligned.m16n8k8.row.col.f32.tf32.tf32.f32 "
                        "{%0,%1,%2,%3}, {%4,%5,%6,%7}, {%8,%9}, {%0,%1,%2,%3};\n"
                        : "+f"(acc[mt][nt][0]), "+f"(acc[mt][nt][1]),
                          "+f"(acc[mt][nt][2]), "+f"(acc[mt][nt][3])
                        : "r"(a[mt][0]), "r"(a[mt][1]), "r"(a[mt][2]), "r"(a[mt][3]),
                          "r"(b[nt][0]), "r"(b[nt][1]));
                }
        }
    }

    // epilogue: bias + store (float2)
    float bb0[4], bb1[4];
    #pragma unroll
    for (int nt = 0; nt < 4; nt++) {
        int col = col0 + wn * 32 + nt * 8 + 2 * lc;
        bb0[nt] = g_bias[col];
        bb1[nt] = g_bias[col + 1];
    }
    #pragma unroll
    for (int mt = 0; mt < 4; mt++) {
        int r0 = row0 + wm * 64 + mt * 16 + lr;
        #pragma unroll
        for (int nt = 0; nt < 4; nt++) {
            int col = col0 + wn * 32 + nt * 8 + 2 * lc;
            *(float2*)&g_pre[(size_t)r0 * G4 + col] =
                make_float2(acc[mt][nt][0] + bb0[nt], acc[mt][nt][1] + bb1[nt]);
            *(float2*)&g_pre[(size_t)(r0 + 8) * G4 + col] =
                make_float2(acc[mt][nt][2] + bb0[nt], acc[mt][nt][3] + bb1[nt]);
        }
    }
}

// ---------------- Kernel 3: persistent LSTM, 2 batch rows / block ----------------
// mask folded into previous step's update; g_pre prefetched one step ahead.
#define RC 64
__global__ __launch_bounds__(512, 1) void lstm_kernel(
    const float* __restrict__ done,
    const float* __restrict__ h0, const float* __restrict__ c0,
    const float* __restrict__ w_hh,
    float* __restrict__ hT, float* __restrict__ cT)
{
    __shared__ float hs[2][128];
    __shared__ float cs[2][128];
    __shared__ float gs[2][512];

    const int tid = threadIdx.x;
    const int b0  = blockIdx.x * 2;

    if (tid < 256) {
        int r = tid >> 7, u = tid & 127;
        float m = 1.f - done[b0 + r];                 // mask for t=0
        hs[r][u] = h0[(b0 + r) * HID + u] * m;
        cs[r][u] = c0[(b0 + r) * HID + u] * m;
    }

    const float* wrow = w_hh + (size_t)tid * HID;
    float wc[RC];
    #pragma unroll
    for (int k = 0; k < RC; k++) wc[k] = wrow[k];
    __syncthreads();

    float a0 = g_pre[(size_t)b0 * G4 + tid];
    float a1 = g_pre[(size_t)(b0 + 1) * G4 + tid];

    for (int t = 0; t < TT; t++) {
        #pragma unroll
        for (int k = 0; k < RC; k++) {
            float w = wc[k];
            a0 = fmaf(w, hs[0][k], a0);
            a1 = fmaf(w, hs[1][k], a1);
        }
        #pragma unroll
        for (int k = RC; k < HID; k += 4) {
            float4 wv = *(const float4*)(wrow + k);
            a0 = fmaf(wv.x, hs[0][k], a0);   a0 = fmaf(wv.y, hs[0][k+1], a0);
            a0 = fmaf(wv.z, hs[0][k+2], a0); a0 = fmaf(wv.w, hs[0][k+3], a0);
            a1 = fmaf(wv.x, hs[1][k], a1);   a1 = fmaf(wv.y, hs[1][k+1], a1);
            a1 = fmaf(wv.z, hs[1][k+2], a1); a1 = fmaf(wv.w, hs[1][k+3], a1);
        }
        gs[0][tid] = a0;
        gs[1][tid] = a1;

        // prefetch next step's pre-activations (independent of smem state)
        if (t + 1 < TT) {
            a0 = g_pre[((size_t)((t + 1) * BB + b0    )) * G4 + tid];
            a1 = g_pre[((size_t)((t + 1) * BB + b0 + 1)) * G4 + tid];
        }
        __syncthreads();

        if (tid < 256) {
            int r = tid >> 7, u = tid & 127;
            float ig = 1.f / (1.f + __expf(-gs[r][u]));
            float fg = 1.f / (1.f + __expf(-gs[r][128 + u]));
            float gg = tanhf(gs[r][256 + u]);
            float og = 1.f / (1.f + __expf(-gs[r][384 + u]));
            float c = fg * cs[r][u] + ig * gg;
            float h = og * tanhf(c);
            g_hid[((size_t)(t * BB + b0 + r)) * HID + u] = h;
            float m = (t + 1 < TT) ? (1.f - done[(t + 1) * BB + b0 + r]) : 1.f;
            cs[r][u] = c * m;
            hs[r][u] = h * m;
        }
        __syncthreads();
    }

    if (tid < 256) {
        int r = tid >> 7, u = tid & 127;
        hT[(b0 + r) * HID + u] = hs[r][u];   // last step unmasked (m=1)
        cT[(b0 + r) * HID + u] = cs[r][u];
    }
}

// ---------------- Kernel 4: heads -> out[N,8] ----------------
__global__ __launch_bounds__(128) void heads_kernel(
    const float* __restrict__ aw, const float* __restrict__ ab,
    const float* __restrict__ cw, const float* __restrict__ cb,
    float* __restrict__ out)
{
    __shared__ __align__(16) float ws [8][132];
    __shared__ __align__(16) float hsm[16][132];
    __shared__ float bs[8];

    const int tid = threadIdx.x;
    const int n0 = blockIdx.x * 16;

    for (int i = tid; i < NA * HID; i += 128) ws[i >> 7][i & 127] = aw[i];
    ws[7][tid] = cw[tid];
    if (tid < NA) bs[tid] = ab[tid];
    if (tid == NA) bs[7] = cb[0];

    for (int i = tid; i < 16 * HID; i += 128)
        hsm[i >> 7][i & 127] = g_hid[(size_t)n0 * HID + i];
    __syncthreads();

    const int s = tid >> 3, col = tid & 7;
    float acc = bs[col];
    const float4* hp = (const float4*)&hsm[s][0];
    const float4* wp = (const float4*)&ws[col][0];
    #pragma unroll
    for (int k = 0; k < 32; k++) {
        float4 h4 = hp[k], w4 = wp[k];
        acc += h4.x * w4.x + h4.y * w4.y + h4.z * w4.z + h4.w * w4.w;
    }
    out[(size_t)(n0 + s) * 8 + col] = acc;
}

// ---------------- launch ----------------
extern "C" void kernel_launch(void* const* d_in, const int* in_sizes, int n_in,
                              void* d_out, int out_size)
{
    const float* obs   = (const float*)d_in[0];
    const float* done  = (const float*)d_in[1];
    const float* h0    = (const float*)d_in[2];
    const float* c0    = (const float*)d_in[3];
    const float* w1    = (const float*)d_in[4];
    const float* b1    = (const float*)d_in[5];
    const float* w2    = (const float*)d_in[6];
    const float* b2    = (const float*)d_in[7];
    const float* w3    = (const float*)d_in[8];
    const float* b3    = (const float*)d_in[9];
    const float* w_ih  = (const float*)d_in[10];
    const float* w_hh  = (const float*)d_in[11];
    const float* b_ih  = (const float*)d_in[12];
    const float* b_hh  = (const float*)d_in[13];
    const float* aw    = (const float*)d_in[14];
    const float* ab    = (const float*)d_in[15];
    const float* cw    = (const float*)d_in[16];
    const float* cb    = (const float*)d_in[17];

    float* out = (float*)d_out;                    // [N, 8]
    float* hT  = out + (size_t)NN * 8;             // [B, HID]
    float* cT  = hT + (size_t)BB * HID;            // [B, HID]

    static bool attr_done = false;
    if (!attr_done) {
        cudaFuncSetAttribute(conv_feat_kernel,
                             cudaFuncAttributeMaxDynamicSharedMemorySize,
                             CV_SMEM_BYTES);
        cudaFuncSetAttribute(gemm_pre_kernel,
                             cudaFuncAttributeMaxDynamicSharedMemorySize,
                             G_SMEM_BYTES);
        attr_done = true;
    }

    prep_kernel<<<(G4 * NFLAT + 255) / 256, 256>>>(w_ih, b_ih, b_hh);

    conv_feat_kernel<<<NN / 4, 256, CV_SMEM_BYTES>>>(obs, w1, b1, w2, b2, w3, b3);

    dim3 ggrid(G4 / 128, NN / 128);
    gemm_pre_kernel<<<ggrid, 256, G_SMEM_BYTES>>>();

    lstm_kernel<<<BB / 2, 512>>>(done, h0, c0, w_hh, hT, cT);

    heads_kernel<<<NN / 16, 128>>>(aw, ab, cw, cb, out);
}